// round 11
// baseline (speedup 1.0000x reference)
#include <cuda_runtime.h>
#include <cuda_fp16.h>
#include <mma.h>
#include <cstdint>
#include <math.h>

using namespace nvcuda;

#define Bsz 4
#define Sq 512
#define Dm 512
#define Hn 8
#define DKh 64
#define Lyr 6
#define DFFn 2048
#define VOCn 50257
#define NTOK (Bsz*Sq)      // 2048
#define VPAD 50432         // 394*128
#define QKVLD 1536

// ---------------- helpers ----------------
__device__ __forceinline__ uint32_t smem_u32(const void* p) {
    uint32_t a;
    asm("{ .reg .u64 t; cvta.to.shared.u64 t, %1; cvt.u32.u64 %0, t; }" : "=r"(a) : "l"(p));
    return a;
}
#define CP_ASYNC16(dst, src) \
    asm volatile("cp.async.cg.shared.global [%0], [%1], 16;" :: "r"(dst), "l"(src))
#define CP_COMMIT()  asm volatile("cp.async.commit_group;" ::: "memory")
#define CP_WAIT(n)   asm volatile("cp.async.wait_group %0;" :: "n"(n) : "memory")

// ---------------- device scratch ----------------
__device__ __half g_x[NTOK*Dm];
__device__ __half g_qkv[(size_t)NTOK*QKVLD];
__device__ __half g_t[NTOK*Dm];
__device__ __half g_tmp[NTOK*Dm];
__device__ __half g_ff[(size_t)NTOK*DFFn];
__device__ __half g_wqkv[(size_t)Lyr*Dm*QKVLD];
__device__ __half g_wo[(size_t)Lyr*Dm*Dm];
__device__ __half g_w1[(size_t)Dm*DFFn];
__device__ __half g_w2[(size_t)DFFn*Dm];
__device__ __half g_wout[(size_t)Dm*VPAD];
__device__ float  g_bqkv[Lyr*QKVLD];
__device__ float  g_bout[VPAD];

// ---------------- merged prep kernel ----------------
// Segment 0: wqkv concat [L*512 rows of 1536]  (L*512*384 float4)
// Segment 1: wo  (L*512*512 /4)
// Segment 2: w1  (512*2048 /4)
// Segment 3: w2  (2048*512 /4)
// Segment 4: bqkv concat (L*1536 floats, handled scalar)
#define P_WQKV ((size_t)Lyr*Dm*(QKVLD/4))
#define P_WO   ((size_t)Lyr*Dm*Dm/4)
#define P_W1   ((size_t)Dm*DFFn/4)
#define P_W2   ((size_t)DFFn*Dm/4)
#define P_TOT  (P_WQKV + P_WO + P_W1 + P_W2)

__global__ void prep_all(const float* __restrict__ Wq, const float* __restrict__ Wk,
                         const float* __restrict__ Wv, const float* __restrict__ Wo,
                         const float* __restrict__ W1, const float* __restrict__ W2,
                         const float* __restrict__ bq, const float* __restrict__ bk,
                         const float* __restrict__ bv,
                         __half* __restrict__ wqkv, __half* __restrict__ wo,
                         __half* __restrict__ w1, __half* __restrict__ w2,
                         float* __restrict__ bqkv) {
    size_t i = (size_t)blockIdx.x * blockDim.x + threadIdx.x;
    if (i < P_WQKV) {
        size_t n4 = i % (QKVLD / 4);
        size_t k  = (i / (QKVLD / 4)) % Dm;
        size_t l  = i / ((size_t)(QKVLD / 4) * Dm);
        const float* src = (n4 < 128) ? Wq : (n4 < 256) ? Wk : Wv;
        size_t nn = (n4 % 128) * 4;
        float4 v = *reinterpret_cast<const float4*>(&src[(l * Dm + k) * Dm + nn]);
        __half2 h0 = __floats2half2_rn(v.x, v.y);
        __half2 h1 = __floats2half2_rn(v.z, v.w);
        reinterpret_cast<uint2*>(wqkv)[i] = make_uint2(*(uint32_t*)&h0, *(uint32_t*)&h1);
        // piggyback bias concat on first L*384 threads
        if (i < (size_t)Lyr * QKVLD / 4) {
            size_t bi = i * 4;
            int l2 = bi / QKVLD, j = bi % QKVLD;
            const float* bsrc = (j < 512) ? bq + l2 * 512 + j
                              : (j < 1024) ? bk + l2 * 512 + j - 512
                                           : bv + l2 * 512 + j - 1024;
            float4 bv4 = *reinterpret_cast<const float4*>(bsrc);
            *reinterpret_cast<float4*>(&bqkv[bi]) = bv4;
        }
        return;
    }
    i -= P_WQKV;
    const float* src; __half* dst; size_t j;
    if (i < P_WO) { src = Wo; dst = wo; j = i; }
    else if (i < P_WO + P_W1) { src = W1; dst = w1; j = i - P_WO; }
    else if (i < P_WO + P_W1 + P_W2) { src = W2; dst = w2; j = i - P_WO - P_W1; }
    else return;
    float4 v = reinterpret_cast<const float4*>(src)[j];
    __half2 h0 = __floats2half2_rn(v.x, v.y);
    __half2 h1 = __floats2half2_rn(v.z, v.w);
    reinterpret_cast<uint2*>(dst)[j] = make_uint2(*(uint32_t*)&h0, *(uint32_t*)&h1);
}

__global__ void pad_cvt_wout(const float* __restrict__ src, __half* __restrict__ dst,
                             const float* __restrict__ bsrc, float* __restrict__ bdst) {
    const size_t total = (size_t)Dm * VPAD;
    for (size_t i = (size_t)blockIdx.x * blockDim.x + threadIdx.x; i < total;
         i += (size_t)gridDim.x * blockDim.x) {
        size_t r = i / VPAD, c = i % VPAD;
        dst[i] = (c < VOCn) ? __float2half(src[r * VOCn + c]) : __half(0.f);
        if (i < VPAD) bdst[i] = (i < VOCn) ? bsrc[i] : 0.f;
    }
}

__global__ void embed_kernel(const int* __restrict__ ids,
                             const float* __restrict__ tok,
                             const float* __restrict__ pos,
                             __half* __restrict__ x) {
    int row = blockIdx.x;
    int s = row % Sq;
    int id = ids[row];
    const float4* t4 = reinterpret_cast<const float4*>(tok) + (size_t)id * (Dm / 4);
    const float4* p4 = reinterpret_cast<const float4*>(pos) + (size_t)s * (Dm / 4);
    int t = threadIdx.x;
    float4 a = t4[t], b = p4[t];
    __half2 h0 = __floats2half2_rn(a.x + b.x, a.y + b.y);
    __half2 h1 = __floats2half2_rn(a.z + b.z, a.w + b.w);
    reinterpret_cast<uint2*>(x + (size_t)row * Dm)[t] = make_uint2(*(uint32_t*)&h0, *(uint32_t*)&h1);
}

// ===== GEMM h4: 128x128, BK=64, 128 thr (4 warps, 64x64 tiles), 2 CTA/SM =====
// smem: A [3][128][72]h (55296B) + B [3][64][144]h (55296B) = 110592B
#define H4_BYTES 110592

template <int ACT, int OUTH>
__global__ __launch_bounds__(128, 2)
void gemm_h4(int K, const __half* __restrict__ A,
             const __half* __restrict__ W, int ldw,
             const float* __restrict__ bias,
             void* __restrict__ Cv, int ldc, int Nc) {
    extern __shared__ char smraw[];
    __half* As = reinterpret_cast<__half*>(smraw);            // [3][128][72]
    __half* Bs = reinterpret_cast<__half*>(smraw + 55296);    // [3][64][144]
    const uint32_t sb = smem_u32(smraw);
    const uint32_t sbB = sb + 55296;

    const int tid = threadIdx.x;
    const int wid = tid >> 5;
    const int wm = wid & 1, wn = wid >> 1;   // 2x2 warps, warp tile 64x64
    const int crow = blockIdx.y * 128;
    const int ccol = blockIdx.x * 128;

    wmma::fragment<wmma::accumulator, 16, 16, 16, float> acc[4][4];
#pragma unroll
    for (int i = 0; i < 4; i++)
#pragma unroll
        for (int j = 0; j < 4; j++) wmma::fill_fragment(acc[i][j], 0.f);

    const __half* Ab = A + (size_t)crow * K;
    const int T = K >> 6;

    auto issue_stage = [&](int st, int t) {
        const int k0 = t << 6;
        // A: 128 rows x 8 segs = 1024 chunks / 128 thr = 8 reps
#pragma unroll
        for (int rep = 0; rep < 8; rep++) {
            int c = rep * 128 + tid;
            int row = c >> 3, seg = c & 7;
            CP_ASYNC16(sb + st * 18432 + row * 144 + seg * 16,
                       &Ab[(size_t)row * K + k0 + seg * 8]);
        }
        // B: 64 rows x 16 segs = 1024 chunks
#pragma unroll
        for (int rep = 0; rep < 8; rep++) {
            int c = rep * 128 + tid;
            int row = c >> 4, seg = c & 15;
            CP_ASYNC16(sbB + st * 18432 + row * 288 + seg * 16,
                       &W[(size_t)(k0 + row) * ldw + ccol + seg * 8]);
        }
        CP_COMMIT();
    };

    issue_stage(0, 0);
    issue_stage(1, 1);

    for (int t = 0; t < T; t++) {
        CP_WAIT(1);
        __syncthreads();
        if (t + 2 < T) issue_stage((t + 2) % 3, t + 2); else CP_COMMIT();
        const int st = t % 3;
        __half* Ast = As + st * 128 * 72;
        __half* Bst = Bs + st * 64 * 144;
#pragma unroll
        for (int ks = 0; ks < 4; ks++) {
            wmma::fragment<wmma::matrix_a, 16, 16, 16, __half, wmma::row_major> af[4];
            wmma::fragment<wmma::matrix_b, 16, 16, 16, __half, wmma::row_major> bf[4];
#pragma unroll
            for (int i = 0; i < 4; i++)
                wmma::load_matrix_sync(af[i], Ast + (wm * 64 + i * 16) * 72 + ks * 16, 72);
#pragma unroll
            for (int j = 0; j < 4; j++)
                wmma::load_matrix_sync(bf[j], Bst + (ks * 16) * 144 + wn * 64 + j * 16, 144);
#pragma unroll
            for (int i = 0; i < 4; i++)
#pragma unroll
                for (int j = 0; j < 4; j++)
                    wmma::mma_sync(acc[i][j], af[i], bf[j], acc[i][j]);
        }
    }

    // epilogue: 4 passes, each stages 32 rows x 128 cols
    float* stg = reinterpret_cast<float*>(smraw);   // [4][16][68]
#pragma unroll
    for (int i = 0; i < 4; i++) {
        __syncthreads();
#pragma unroll
        for (int j = 0; j < 4; j++)
            wmma::store_matrix_sync(stg + wid * 1088 + j * 16, acc[i][j], 68, wmma::mem_row_major);
        __syncthreads();
#pragma unroll
        for (int it = 0; it < 8; it++) {
            int idx = it * 128 + tid;            // 1024 float4 = 32 rows x 32 c4
            int r = idx >> 5;
            int c4 = (idx & 31) * 4;
            int wmg = r >> 4, rr = r & 15;
            int wng = c4 >> 6, cc = c4 & 63;
            const float* sp = stg + (wng * 2 + wmg) * 1088 + rr * 68 + cc;
            int row = crow + wmg * 64 + i * 16 + rr;
            int colb = ccol + c4;
            float4 bvv = *reinterpret_cast<const float4*>(&bias[colb]);
            float v0 = sp[0] + bvv.x, v1 = sp[1] + bvv.y;
            float v2 = sp[2] + bvv.z, v3 = sp[3] + bvv.w;
            if (ACT == 1) {
                v0 = 0.5f * v0 * (1.0f + erff(v0 * 0.70710678118654752f));
                v1 = 0.5f * v1 * (1.0f + erff(v1 * 0.70710678118654752f));
                v2 = 0.5f * v2 * (1.0f + erff(v2 * 0.70710678118654752f));
                v3 = 0.5f * v3 * (1.0f + erff(v3 * 0.70710678118654752f));
            }
            if (OUTH == 1) {
                __half* C = reinterpret_cast<__half*>(Cv);
                __half2 h0 = __floats2half2_rn(v0, v1);
                __half2 h1 = __floats2half2_rn(v2, v3);
                *reinterpret_cast<uint2*>(&C[(size_t)row * ldc + colb]) =
                    make_uint2(*(uint32_t*)&h0, *(uint32_t*)&h1);
            } else {
                float* C = reinterpret_cast<float*>(Cv);
                float* cp = &C[(size_t)row * ldc + colb];
                if (colb + 0 < Nc) cp[0] = v0;
                if (colb + 1 < Nc) cp[1] = v1;
                if (colb + 2 < Nc) cp[2] = v2;
                if (colb + 3 < Nc) cp[3] = v3;
            }
        }
    }
}

// ================= GEMM h3: 64x128, BK=32, half, 3 CTA/SM =================
#define H3_BYTES 43008

template <int ACT>
__global__ __launch_bounds__(128, 3)
void gemm_h3(int K, const __half* __restrict__ A,
             const __half* __restrict__ W, int ldw,
             const float* __restrict__ bias,
             __half* __restrict__ C, int ldc) {
    extern __shared__ char smraw[];
    __half* As = reinterpret_cast<__half*>(smraw);            // [3][64][40]
    __half* Bs = reinterpret_cast<__half*>(smraw + 15360);    // [3][32][144]
    const uint32_t sb = smem_u32(smraw);
    const uint32_t sbB = sb + 15360;

    const int tid = threadIdx.x;
    const int wid = tid >> 5;
    const int wm = wid & 1, wn = wid >> 1;
    const int crow = blockIdx.y * 64;
    const int ccol = blockIdx.x * 128;

    wmma::fragment<wmma::accumulator, 16, 16, 16, float> acc[2][4];
#pragma unroll
    for (int i = 0; i < 2; i++)
#pragma unroll
        for (int j = 0; j < 4; j++) wmma::fill_fragment(acc[i][j], 0.f);

    const __half* Ab = A + (size_t)crow * K;
    const int T = K >> 5;

    auto issue_stage = [&](int st, int t) {
        const int k0 = t << 5;
#pragma unroll
        for (int rep = 0; rep < 2; rep++) {
            int c = rep * 128 + tid;
            int row = c >> 2, seg = c & 3;
            CP_ASYNC16(sb + st * 5120 + row * 80 + seg * 16,
                       &Ab[(size_t)row * K + k0 + seg * 8]);
        }
#pragma unroll
        for (int rep = 0; rep < 4; rep++) {
            int c = rep * 128 + tid;
            int row = c >> 4, seg = c & 15;
            CP_ASYNC16(sbB + st * 9216 + row * 288 + seg * 16,
                       &W[(size_t)(k0 + row) * ldw + ccol + seg * 8]);
        }
        CP_COMMIT();
    };

    issue_stage(0, 0);
    issue_stage(1, 1);

    for (int t = 0; t < T; t++) {
        CP_WAIT(1);
        __syncthreads();
        if (t + 2 < T) issue_stage((t + 2) % 3, t + 2); else CP_COMMIT();
        const int st = t % 3;
        __half* Ast = As + st * 64 * 40;
        __half* Bst = Bs + st * 32 * 144;
#pragma unroll
        for (int ks = 0; ks < 2; ks++) {
            wmma::fragment<wmma::matrix_a, 16, 16, 16, __half, wmma::row_major> af[2];
            wmma::fragment<wmma::matrix_b, 16, 16, 16, __half, wmma::row_major> bf[4];
#pragma unroll
            for (int i = 0; i < 2; i++)
                wmma::load_matrix_sync(af[i], Ast + (wm * 32 + i * 16) * 40 + ks * 16, 40);
#pragma unroll
            for (int j = 0; j < 4; j++)
                wmma::load_matrix_sync(bf[j], Bst + (ks * 16) * 144 + wn * 64 + j * 16, 144);
#pragma unroll
            for (int i = 0; i < 2; i++)
#pragma unroll
                for (int j = 0; j < 4; j++)
                    wmma::mma_sync(acc[i][j], af[i], bf[j], acc[i][j]);
        }
    }

    float* stg = reinterpret_cast<float*>(smraw);
#pragma unroll
    for (int i = 0; i < 2; i++) {
        __syncthreads();
#pragma unroll
        for (int j = 0; j < 4; j++)
            wmma::store_matrix_sync(stg + wid * 1088 + j * 16, acc[i][j], 68, wmma::mem_row_major);
        __syncthreads();
#pragma unroll
        for (int it = 0; it < 8; it++) {
            int idx = it * 128 + tid;
            int r = idx >> 5;
            int c4 = (idx & 31) * 4;
            int wmg = r >> 4, rr = r & 15;
            int wng = c4 >> 6, cc = c4 & 63;
            const float* sp = stg + (wng * 2 + wmg) * 1088 + rr * 68 + cc;
            int row = crow + wmg * 32 + i * 16 + rr;
            int colb = ccol + c4;
            float4 bvv = *reinterpret_cast<const float4*>(&bias[colb]);
            float v0 = sp[0] + bvv.x, v1 = sp[1] + bvv.y;
            float v2 = sp[2] + bvv.z, v3 = sp[3] + bvv.w;
            if (ACT == 1) {
                v0 = 0.5f * v0 * (1.0f + erff(v0 * 0.70710678118654752f));
                v1 = 0.5f * v1 * (1.0f + erff(v1 * 0.70710678118654752f));
                v2 = 0.5f * v2 * (1.0f + erff(v2 * 0.70710678118654752f));
                v3 = 0.5f * v3 * (1.0f + erff(v3 * 0.70710678118654752f));
            }
            __half2 h0 = __floats2half2_rn(v0, v1);
            __half2 h1 = __floats2half2_rn(v2, v3);
            *reinterpret_cast<uint2*>(&C[(size_t)row * ldc + colb]) =
                make_uint2(*(uint32_t*)&h0, *(uint32_t*)&h1);
        }
    }
}

// ================= fused attention: q-tile 32, 2 CTA/SM =================
#define ATT_SLD 516
#define ATT_PLD 528
#define ATT_BYTES (32*ATT_SLD*4 + 32*ATT_PLD*2)

__global__ __launch_bounds__(256, 2)
void attn_fused(const __half* __restrict__ QKV, __half* __restrict__ O) {
    extern __shared__ char sm[];
    float* Ssm = reinterpret_cast<float*>(sm);
    __half* Psm = reinterpret_cast<__half*>(sm + 32 * ATT_SLD * 4);

    const int tid = threadIdx.x;
    const int wid = tid >> 5, lane = tid & 31;
    const int bh = blockIdx.y;
    const int b = bh >> 3, h = bh & 7;
    const int q0 = blockIdx.x * 32;

    const __half* qb = QKV + (size_t)b * Sq * QKVLD + h * DKh;
    const __half* kb = QKV + (size_t)b * Sq * QKVLD + 512 + h * DKh;
    const __half* vb = QKV + (size_t)b * Sq * QKVLD + 1024 + h * DKh;

    {
        const int wq = wid & 1, wk = wid >> 1;
        wmma::fragment<wmma::accumulator, 16, 16, 16, float> acc[8];
#pragma unroll
        for (int j = 0; j < 8; j++) wmma::fill_fragment(acc[j], 0.f);

#pragma unroll
        for (int d0 = 0; d0 < DKh; d0 += 16) {
            wmma::fragment<wmma::matrix_a, 16, 16, 16, __half, wmma::row_major> af;
            wmma::load_matrix_sync(af, &qb[(size_t)(q0 + wq * 16) * QKVLD + d0], QKVLD);
#pragma unroll
            for (int j = 0; j < 8; j++) {
                wmma::fragment<wmma::matrix_b, 16, 16, 16, __half, wmma::col_major> bf;
                wmma::load_matrix_sync(bf, &kb[(size_t)(wk * 128 + j * 16) * QKVLD + d0], QKVLD);
                wmma::mma_sync(acc[j], af, bf, acc[j]);
            }
        }
#pragma unroll
        for (int j = 0; j < 8; j++) {
#pragma unroll
            for (int e = 0; e < acc[j].num_elements; e++) acc[j].x[e] *= 0.125f;
            wmma::store_matrix_sync(&Ssm[(wq * 16) * ATT_SLD + wk * 128 + j * 16],
                                    acc[j], ATT_SLD, wmma::mem_row_major);
        }
    }
    __syncthreads();

    {
        const int row = wid * 4 + (lane >> 3);
        const int sub = lane & 7;
        const float* srow = Ssm + row * ATT_SLD;
        __half* prow = Psm + row * ATT_PLD;

        float mx = -1e30f;
#pragma unroll 8
        for (int i = 0; i < 64; i++) mx = fmaxf(mx, srow[sub + 8 * i]);
        mx = fmaxf(mx, __shfl_xor_sync(0xffffffffu, mx, 1));
        mx = fmaxf(mx, __shfl_xor_sync(0xffffffffu, mx, 2));
        mx = fmaxf(mx, __shfl_xor_sync(0xffffffffu, mx, 4));

        float sum = 0.f;
#pragma unroll 8
        for (int i = 0; i < 64; i++) {
            float e = __expf(srow[sub + 8 * i] - mx);
            sum += e;
            prow[sub + 8 * i] = __float2half(e);
        }
        sum += __shfl_xor_sync(0xffffffffu, sum, 1);
        sum += __shfl_xor_sync(0xffffffffu, sum, 2);
        sum += __shfl_xor_sync(0xffffffffu, sum, 4);
        float inv = 1.0f / sum;
#pragma unroll 8
        for (int i = 0; i < 64; i++) {
            int c = sub + 8 * i;
            prow[c] = __float2half(__half2float(prow[c]) * inv);
        }
    }
    __syncthreads();

    {
        const int wq = wid & 1, wd = wid >> 1;
        wmma::fragment<wmma::accumulator, 16, 16, 16, float> acc;
        wmma::fill_fragment(acc, 0.f);

        for (int k0 = 0; k0 < Sq; k0 += 16) {
            wmma::fragment<wmma::matrix_a, 16, 16, 16, __half, wmma::row_major> af;
            wmma::fragment<wmma::matrix_b, 16, 16, 16, __half, wmma::row_major> bf;
            wmma::load_matrix_sync(af, &Psm[(wq * 16) * ATT_PLD + k0], ATT_PLD);
            wmma::load_matrix_sync(bf, &vb[(size_t)k0 * QKVLD + wd * 16], QKVLD);
            wmma::mma_sync(acc, af, bf, acc);
        }
        float* stg = Ssm;
        wmma::store_matrix_sync(&stg[(wq * 16) * 68 + wd * 16], acc, 68, wmma::mem_row_major);
    }
    __syncthreads();
    {
        float* stg = Ssm;
        __half* ob = O + (size_t)b * Sq * Dm + h * DKh;
#pragma unroll
        for (int it = 0; it < 4; it++) {
            int idx = it * 256 + tid;
            int r = idx >> 5, c2 = idx & 31;
            __half2 hh = __floats2half2_rn(stg[r * 68 + c2 * 2], stg[r * 68 + c2 * 2 + 1]);
            *reinterpret_cast<uint32_t*>(&ob[(size_t)(q0 + r) * Dm + c2 * 2]) = *(uint32_t*)&hh;
        }
    }
}

// ================= warp-per-row LayerNorm =================
__global__ __launch_bounds__(256)
void ln_kernel(const __half* __restrict__ a, const __half* __restrict__ res,
               const float* __restrict__ g, const float* __restrict__ beta,
               __half* __restrict__ out) {
    const int wid = threadIdx.x >> 5, lane = threadIdx.x & 31;
    const size_t row = blockIdx.x * 8 + wid;
    const __half2* a2 = reinterpret_cast<const __half2*>(a + row * Dm);
    const __half2* r2 = res ? reinterpret_cast<const __half2*>(res + row * Dm) : nullptr;

    float v[16];
    float s = 0.f, sq = 0.f;
#pragma unroll
    for (int k = 0; k < 8; k++) {
        int i = lane + 32 * k;
        __half2 h = a2[i];
        float x0 = __half2float(__low2half(h)), x1 = __half2float(__high2half(h));
        if (r2) {
            __half2 rr = r2[i];
            x0 += __half2float(__low2half(rr));
            x1 += __half2float(__high2half(rr));
        }
        v[2 * k] = x0; v[2 * k + 1] = x1;
        s += x0 + x1;
        sq += x0 * x0 + x1 * x1;
    }
#pragma unroll
    for (int o = 16; o; o >>= 1) {
        s  += __shfl_xor_sync(0xffffffffu, s, o);
        sq += __shfl_xor_sync(0xffffffffu, sq, o);
    }
    float mean = s * (1.0f / Dm);
    float var = sq * (1.0f / Dm) - mean * mean;
    float inv = rsqrtf(var + 1e-5f);

    const float2* gf = reinterpret_cast<const float2*>(g);
    const float2* bf = reinterpret_cast<const float2*>(beta);
    __half2* o2 = reinterpret_cast<__half2*>(out + row * Dm);
#pragma unroll
    for (int k = 0; k < 8; k++) {
        int i = lane + 32 * k;
        float2 gg = gf[i], bb = bf[i];
        float y0 = (v[2 * k]     - mean) * inv * gg.x + bb.x;
        float y1 = (v[2 * k + 1] - mean) * inv * gg.y + bb.y;
        o2[i] = __floats2half2_rn(y0, y1);
    }
}

// ================= orchestration =================
extern "C" void kernel_launch(void* const* d_in, const int* in_sizes, int n_in,
                              void* d_out, int out_size) {
    const int*   ids  = (const int*)  d_in[0];
    const float* tok  = (const float*)d_in[1];
    const float* pos  = (const float*)d_in[2];
    const float* Wq   = (const float*)d_in[3];
    const float* bq   = (const float*)d_in[4];
    const float* Wk   = (const float*)d_in[5];
    const float* bk   = (const float*)d_in[6];
    const float* Wv   = (const float*)d_in[7];
    const float* bv   = (const float*)d_in[8];
    const float* Wo   = (const float*)d_in[9];
    const float* bo   = (const float*)d_in[10];
    const float* ln_g = (const float*)d_in[11];
    const float* ln_b = (const float*)d_in[12];
    const float* W1   = (const float*)d_in[13];
    const float* b1   = (const float*)d_in[14];
    const float* W2   = (const float*)d_in[15];
    const float* b2   = (const float*)d_in[16];
    const float* on_g = (const float*)d_in[17];
    const float* on_b = (const float*)d_in[18];
    const float* Wout = (const float*)d_in[19];
    const float* bout = (const float*)d_in[20];
    float* out = (float*)d_out;

    __half *x, *qkv, *t, *tmp, *ff, *wqkv, *wo, *w1, *w2, *wout;
    float *bqkv, *boutp;
    cudaGetSymbolAddress((void**)&x,     g_x);
    cudaGetSymbolAddress((void**)&qkv,   g_qkv);
    cudaGetSymbolAddress((void**)&t,     g_t);
    cudaGetSymbolAddress((void**)&tmp,   g_tmp);
    cudaGetSymbolAddress((void**)&ff,    g_ff);
    cudaGetSymbolAddress((void**)&wqkv,  g_wqkv);
    cudaGetSymbolAddress((void**)&wo,    g_wo);
    cudaGetSymbolAddress((void**)&w1,    g_w1);
    cudaGetSymbolAddress((void**)&w2,    g_w2);
    cudaGetSymbolAddress((void**)&wout,  g_wout);
    cudaGetSymbolAddress((void**)&bqkv,  g_bqkv);
    cudaGetSymbolAddress((void**)&boutp, g_bout);

    cudaFuncSetAttribute(gemm_h4<0,0>, cudaFuncAttributeMaxDynamicSharedMemorySize, H4_BYTES);
    cudaFuncSetAttribute(gemm_h4<1,1>, cudaFuncAttributeMaxDynamicSharedMemorySize, H4_BYTES);
    cudaFuncSetAttribute(gemm_h4<0,1>, cudaFuncAttributeMaxDynamicSharedMemorySize, H4_BYTES);
    cudaFuncSetAttribute(gemm_h3<0>,   cudaFuncAttributeMaxDynamicSharedMemorySize, H3_BYTES);
    cudaFuncSetAttribute(attn_fused,   cudaFuncAttributeMaxDynamicSharedMemorySize, ATT_BYTES);

    // ---- prep (2 launches) ----
    prep_all<<<(unsigned)((P_TOT + 255) / 256), 256>>>(
        Wq, Wk, Wv, Wo, W1, W2, bq, bk, bv, wqkv, wo, w1, w2, bqkv);
    pad_cvt_wout<<<4096, 256>>>(Wout, wout, bout, boutp);

    embed_kernel<<<NTOK, 128>>>(ids, tok, pos, x);

    for (int l = 0; l < Lyr; l++) {
        const size_t bOff = (size_t)l * Dm;
        // QKV via h4: grid (12, 16) = 192 CTAs, 2/SM single wave
        gemm_h4<0,1><<<dim3(QKVLD / 128, NTOK / 128), 128, H4_BYTES>>>(
            Dm, x, wqkv + (size_t)l * Dm * QKVLD, QKVLD,
            bqkv + (size_t)l * QKVLD, qkv, QKVLD, QKVLD);

        attn_fused<<<dim3(Sq / 32, Bsz * Hn), 256, ATT_BYTES>>>(qkv, t);

        gemm_h3<0><<<dim3(Dm / 128, NTOK / 64), 128, H3_BYTES>>>(
            Dm, t, wo + (size_t)l * Dm * Dm, Dm, bo + bOff, tmp, Dm);
        ln_kernel<<<NTOK / 8, 256>>>(x, tmp, ln_g + bOff, ln_b + bOff, x);
    }

    // FFN1 via h4: grid (16, 16)
    gemm_h4<1,1><<<dim3(DFFn / 128, NTOK / 128), 128, H4_BYTES>>>(
        Dm, x, w1, DFFn, b1, ff, DFFn, DFFn);
    gemm_h3<0><<<dim3(Dm / 128, NTOK / 64), 128, H3_BYTES>>>(
        DFFn, ff, w2, Dm, b2, t, Dm);
    ln_kernel<<<NTOK / 8, 256>>>(t, nullptr, on_g, on_b, x);

    // logits via h4: grid (394, 16)
    gemm_h4<0,0><<<dim3(VPAD / 128, NTOK / 128), 128, H4_BYTES>>>(
        Dm, x, wout, VPAD, boutp, out, VOCn, VOCn);
}

// round 12
// speedup vs baseline: 1.0473x; 1.0473x over previous
#include <cuda_runtime.h>
#include <cuda_fp16.h>
#include <mma.h>
#include <cstdint>
#include <math.h>

using namespace nvcuda;

#define Bsz 4
#define Sq 512
#define Dm 512
#define Hn 8
#define DKh 64
#define Lyr 6
#define DFFn 2048
#define VOCn 50257
#define NTOK (Bsz*Sq)      // 2048
#define VPAD 50432         // 394*128
#define QKVLD 1536

// ---------------- helpers ----------------
__device__ __forceinline__ uint32_t smem_u32(const void* p) {
    uint32_t a;
    asm("{ .reg .u64 t; cvta.to.shared.u64 t, %1; cvt.u32.u64 %0, t; }" : "=r"(a) : "l"(p));
    return a;
}
#define CP_ASYNC16(dst, src) \
    asm volatile("cp.async.cg.shared.global [%0], [%1], 16;" :: "r"(dst), "l"(src))
#define CP_COMMIT()  asm volatile("cp.async.commit_group;" ::: "memory")
#define CP_WAIT(n)   asm volatile("cp.async.wait_group %0;" :: "n"(n) : "memory")

// B tile smem stride: 152 halves = 304B = 76 words; 76 mod 32 = 12 ->
// ldmatrix row addresses per 8-row phase hit banks {0,12,24,4,16,28,8,20}: conflict-free.
#define BSKEW 152

// ---------------- device scratch ----------------
__device__ __half g_x[NTOK*Dm];
__device__ __half g_qkv[(size_t)NTOK*QKVLD];
__device__ __half g_t[NTOK*Dm];
__device__ __half g_tmp[NTOK*Dm];
__device__ __half g_ff[(size_t)NTOK*DFFn];
__device__ __half g_wqkv[(size_t)Lyr*Dm*QKVLD];
__device__ __half g_wo[(size_t)Lyr*Dm*Dm];
__device__ __half g_w1[(size_t)Dm*DFFn];
__device__ __half g_w2[(size_t)DFFn*Dm];
__device__ __half g_wout[(size_t)Dm*VPAD];
__device__ float  g_bqkv[Lyr*QKVLD];
__device__ float  g_bout[VPAD];

// ---------------- merged prep kernel ----------------
#define P_WQKV ((size_t)Lyr*Dm*(QKVLD/4))
#define P_WO   ((size_t)Lyr*Dm*Dm/4)
#define P_W1   ((size_t)Dm*DFFn/4)
#define P_W2   ((size_t)DFFn*Dm/4)
#define P_TOT  (P_WQKV + P_WO + P_W1 + P_W2)

__global__ void prep_all(const float* __restrict__ Wq, const float* __restrict__ Wk,
                         const float* __restrict__ Wv, const float* __restrict__ Wo,
                         const float* __restrict__ W1, const float* __restrict__ W2,
                         const float* __restrict__ bq, const float* __restrict__ bk,
                         const float* __restrict__ bv,
                         __half* __restrict__ wqkv, __half* __restrict__ wo,
                         __half* __restrict__ w1, __half* __restrict__ w2,
                         float* __restrict__ bqkv) {
    size_t i = (size_t)blockIdx.x * blockDim.x + threadIdx.x;
    if (i < P_WQKV) {
        size_t n4 = i % (QKVLD / 4);
        size_t k  = (i / (QKVLD / 4)) % Dm;
        size_t l  = i / ((size_t)(QKVLD / 4) * Dm);
        const float* src = (n4 < 128) ? Wq : (n4 < 256) ? Wk : Wv;
        size_t nn = (n4 % 128) * 4;
        float4 v = *reinterpret_cast<const float4*>(&src[(l * Dm + k) * Dm + nn]);
        __half2 h0 = __floats2half2_rn(v.x, v.y);
        __half2 h1 = __floats2half2_rn(v.z, v.w);
        reinterpret_cast<uint2*>(wqkv)[i] = make_uint2(*(uint32_t*)&h0, *(uint32_t*)&h1);
        if (i < (size_t)Lyr * QKVLD / 4) {
            size_t bi = i * 4;
            int l2 = bi / QKVLD, j = bi % QKVLD;
            const float* bsrc = (j < 512) ? bq + l2 * 512 + j
                              : (j < 1024) ? bk + l2 * 512 + j - 512
                                           : bv + l2 * 512 + j - 1024;
            float4 bv4 = *reinterpret_cast<const float4*>(bsrc);
            *reinterpret_cast<float4*>(&bqkv[bi]) = bv4;
        }
        return;
    }
    i -= P_WQKV;
    const float* src; __half* dst; size_t j;
    if (i < P_WO) { src = Wo; dst = wo; j = i; }
    else if (i < P_WO + P_W1) { src = W1; dst = w1; j = i - P_WO; }
    else if (i < P_WO + P_W1 + P_W2) { src = W2; dst = w2; j = i - P_WO - P_W1; }
    else return;
    float4 v = reinterpret_cast<const float4*>(src)[j];
    __half2 h0 = __floats2half2_rn(v.x, v.y);
    __half2 h1 = __floats2half2_rn(v.z, v.w);
    reinterpret_cast<uint2*>(dst)[j] = make_uint2(*(uint32_t*)&h0, *(uint32_t*)&h1);
}

__global__ void pad_cvt_wout(const float* __restrict__ src, __half* __restrict__ dst,
                             const float* __restrict__ bsrc, float* __restrict__ bdst) {
    const size_t total = (size_t)Dm * VPAD;
    for (size_t i = (size_t)blockIdx.x * blockDim.x + threadIdx.x; i < total;
         i += (size_t)gridDim.x * blockDim.x) {
        size_t r = i / VPAD, c = i % VPAD;
        dst[i] = (c < VOCn) ? __float2half(src[r * VOCn + c]) : __half(0.f);
        if (i < VPAD) bdst[i] = (i < VOCn) ? bsrc[i] : 0.f;
    }
}

__global__ void embed_kernel(const int* __restrict__ ids,
                             const float* __restrict__ tok,
                             const float* __restrict__ pos,
                             __half* __restrict__ x) {
    int row = blockIdx.x;
    int s = row % Sq;
    int id = ids[row];
    const float4* t4 = reinterpret_cast<const float4*>(tok) + (size_t)id * (Dm / 4);
    const float4* p4 = reinterpret_cast<const float4*>(pos) + (size_t)s * (Dm / 4);
    int t = threadIdx.x;
    float4 a = t4[t], b = p4[t];
    __half2 h0 = __floats2half2_rn(a.x + b.x, a.y + b.y);
    __half2 h1 = __floats2half2_rn(a.z + b.z, a.w + b.w);
    reinterpret_cast<uint2*>(x + (size_t)row * Dm)[t] = make_uint2(*(uint32_t*)&h0, *(uint32_t*)&h1);
}

// ===== GEMM h4: 128x128, BK=32, 128 thr (4 warps, 64x64 tiles), 2 CTA/SM =====
// smem: A [3][128][40]h (30720B) + B [3][32][152]h (29184B) = 59904B
#define H4_A_BYTES 30720
#define H4_BYTES (30720 + 3*32*BSKEW*2)

template <int ACT, int OUTH>
__global__ __launch_bounds__(128, 2)
void gemm_h4(int K, const __half* __restrict__ A,
             const __half* __restrict__ W, int ldw,
             const float* __restrict__ bias,
             void* __restrict__ Cv, int ldc, int Nc) {
    extern __shared__ char smraw[];
    __half* As = reinterpret_cast<__half*>(smraw);              // [3][128][40]
    __half* Bs = reinterpret_cast<__half*>(smraw + H4_A_BYTES); // [3][32][152]
    const uint32_t sb = smem_u32(smraw);
    const uint32_t sbB = sb + H4_A_BYTES;

    const int tid = threadIdx.x;
    const int wid = tid >> 5;
    const int wm = wid & 1, wn = wid >> 1;   // 2x2 warps, warp tile 64x64
    const int crow = blockIdx.y * 128;
    const int ccol = blockIdx.x * 128;

    wmma::fragment<wmma::accumulator, 16, 16, 16, float> acc[4][4];
#pragma unroll
    for (int i = 0; i < 4; i++)
#pragma unroll
        for (int j = 0; j < 4; j++) wmma::fill_fragment(acc[i][j], 0.f);

    const __half* Ab = A + (size_t)crow * K;
    const int T = K >> 5;

    auto issue_stage = [&](int st, int t) {
        const int k0 = t << 5;
        // A: 128 rows x 4 segs = 512 chunks
#pragma unroll
        for (int rep = 0; rep < 4; rep++) {
            int c = rep * 128 + tid;
            int row = c >> 2, seg = c & 3;
            CP_ASYNC16(sb + st * 10240 + row * 80 + seg * 16,
                       &Ab[(size_t)row * K + k0 + seg * 8]);
        }
        // B: 32 rows x 16 segs = 512 chunks
#pragma unroll
        for (int rep = 0; rep < 4; rep++) {
            int c = rep * 128 + tid;
            int row = c >> 4, seg = c & 15;
            CP_ASYNC16(sbB + st * (32 * BSKEW * 2) + row * (BSKEW * 2) + seg * 16,
                       &W[(size_t)(k0 + row) * ldw + ccol + seg * 8]);
        }
        CP_COMMIT();
    };

    issue_stage(0, 0);
    issue_stage(1, 1);

    for (int t = 0; t < T; t++) {
        CP_WAIT(1);
        __syncthreads();
        if (t + 2 < T) issue_stage((t + 2) % 3, t + 2); else CP_COMMIT();
        const int st = t % 3;
        __half* Ast = As + st * 128 * 40;
        __half* Bst = Bs + st * 32 * BSKEW;
#pragma unroll
        for (int ks = 0; ks < 2; ks++) {
            wmma::fragment<wmma::matrix_a, 16, 16, 16, __half, wmma::row_major> af[4];
            wmma::fragment<wmma::matrix_b, 16, 16, 16, __half, wmma::row_major> bf[4];
#pragma unroll
            for (int i = 0; i < 4; i++)
                wmma::load_matrix_sync(af[i], Ast + (wm * 64 + i * 16) * 40 + ks * 16, 40);
#pragma unroll
            for (int j = 0; j < 4; j++)
                wmma::load_matrix_sync(bf[j], Bst + (ks * 16) * BSKEW + wn * 64 + j * 16, BSKEW);
#pragma unroll
            for (int i = 0; i < 4; i++)
#pragma unroll
                for (int j = 0; j < 4; j++)
                    wmma::mma_sync(acc[i][j], af[i], bf[j], acc[i][j]);
        }
    }

    // epilogue: 4 passes, each stages 32 rows x 128 cols
    float* stg = reinterpret_cast<float*>(smraw);   // [4][16][68]
#pragma unroll
    for (int i = 0; i < 4; i++) {
        __syncthreads();
#pragma unroll
        for (int j = 0; j < 4; j++)
            wmma::store_matrix_sync(stg + wid * 1088 + j * 16, acc[i][j], 68, wmma::mem_row_major);
        __syncthreads();
#pragma unroll
        for (int it = 0; it < 8; it++) {
            int idx = it * 128 + tid;            // 1024 float4 = 32 rows x 32 c4
            int r = idx >> 5;
            int c4 = (idx & 31) * 4;
            int wmg = r >> 4, rr = r & 15;
            int wng = c4 >> 6, cc = c4 & 63;
            const float* sp = stg + (wng * 2 + wmg) * 1088 + rr * 68 + cc;
            int row = crow + wmg * 64 + i * 16 + rr;
            int colb = ccol + c4;
            float4 bvv = *reinterpret_cast<const float4*>(&bias[colb]);
            float v0 = sp[0] + bvv.x, v1 = sp[1] + bvv.y;
            float v2 = sp[2] + bvv.z, v3 = sp[3] + bvv.w;
            if (ACT == 1) {
                v0 = 0.5f * v0 * (1.0f + erff(v0 * 0.70710678118654752f));
                v1 = 0.5f * v1 * (1.0f + erff(v1 * 0.70710678118654752f));
                v2 = 0.5f * v2 * (1.0f + erff(v2 * 0.70710678118654752f));
                v3 = 0.5f * v3 * (1.0f + erff(v3 * 0.70710678118654752f));
            }
            if (OUTH == 1) {
                __half* C = reinterpret_cast<__half*>(Cv);
                __half2 h0 = __floats2half2_rn(v0, v1);
                __half2 h1 = __floats2half2_rn(v2, v3);
                *reinterpret_cast<uint2*>(&C[(size_t)row * ldc + colb]) =
                    make_uint2(*(uint32_t*)&h0, *(uint32_t*)&h1);
            } else {
                float* C = reinterpret_cast<float*>(Cv);
                float* cp = &C[(size_t)row * ldc + colb];
                if (colb + 0 < Nc) cp[0] = v0;
                if (colb + 1 < Nc) cp[1] = v1;
                if (colb + 2 < Nc) cp[2] = v2;
                if (colb + 3 < Nc) cp[3] = v3;
            }
        }
    }
}

// ================= GEMM h3: 64x128, BK=32, half, 3 CTA/SM =================
// smem: A [3][64][40]h (15360B) + B [3][32][152]h (29184B) = 44544B
#define H3_A_BYTES 15360
#define H3_BYTES (15360 + 3*32*BSKEW*2)

template <int ACT>
__global__ __launch_bounds__(128, 3)
void gemm_h3(int K, const __half* __restrict__ A,
             const __half* __restrict__ W, int ldw,
             const float* __restrict__ bias,
             __half* __restrict__ C, int ldc) {
    extern __shared__ char smraw[];
    __half* As = reinterpret_cast<__half*>(smraw);              // [3][64][40]
    __half* Bs = reinterpret_cast<__half*>(smraw + H3_A_BYTES); // [3][32][152]
    const uint32_t sb = smem_u32(smraw);
    const uint32_t sbB = sb + H3_A_BYTES;

    const int tid = threadIdx.x;
    const int wid = tid >> 5;
    const int wm = wid & 1, wn = wid >> 1;
    const int crow = blockIdx.y * 64;
    const int ccol = blockIdx.x * 128;

    wmma::fragment<wmma::accumulator, 16, 16, 16, float> acc[2][4];
#pragma unroll
    for (int i = 0; i < 2; i++)
#pragma unroll
        for (int j = 0; j < 4; j++) wmma::fill_fragment(acc[i][j], 0.f);

    const __half* Ab = A + (size_t)crow * K;
    const int T = K >> 5;

    auto issue_stage = [&](int st, int t) {
        const int k0 = t << 5;
#pragma unroll
        for (int rep = 0; rep < 2; rep++) {
            int c = rep * 128 + tid;
            int row = c >> 2, seg = c & 3;
            CP_ASYNC16(sb + st * 5120 + row * 80 + seg * 16,
                       &Ab[(size_t)row * K + k0 + seg * 8]);
        }
#pragma unroll
        for (int rep = 0; rep < 4; rep++) {
            int c = rep * 128 + tid;
            int row = c >> 4, seg = c & 15;
            CP_ASYNC16(sbB + st * (32 * BSKEW * 2) + row * (BSKEW * 2) + seg * 16,
                       &W[(size_t)(k0 + row) * ldw + ccol + seg * 8]);
        }
        CP_COMMIT();
    };

    issue_stage(0, 0);
    issue_stage(1, 1);

    for (int t = 0; t < T; t++) {
        CP_WAIT(1);
        __syncthreads();
        if (t + 2 < T) issue_stage((t + 2) % 3, t + 2); else CP_COMMIT();
        const int st = t % 3;
        __half* Ast = As + st * 64 * 40;
        __half* Bst = Bs + st * 32 * BSKEW;
#pragma unroll
        for (int ks = 0; ks < 2; ks++) {
            wmma::fragment<wmma::matrix_a, 16, 16, 16, __half, wmma::row_major> af[2];
            wmma::fragment<wmma::matrix_b, 16, 16, 16, __half, wmma::row_major> bf[4];
#pragma unroll
            for (int i = 0; i < 2; i++)
                wmma::load_matrix_sync(af[i], Ast + (wm * 32 + i * 16) * 40 + ks * 16, 40);
#pragma unroll
            for (int j = 0; j < 4; j++)
                wmma::load_matrix_sync(bf[j], Bst + (ks * 16) * BSKEW + wn * 64 + j * 16, BSKEW);
#pragma unroll
            for (int i = 0; i < 2; i++)
#pragma unroll
                for (int j = 0; j < 4; j++)
                    wmma::mma_sync(acc[i][j], af[i], bf[j], acc[i][j]);
        }
    }

    float* stg = reinterpret_cast<float*>(smraw);
#pragma unroll
    for (int i = 0; i < 2; i++) {
        __syncthreads();
#pragma unroll
        for (int j = 0; j < 4; j++)
            wmma::store_matrix_sync(stg + wid * 1088 + j * 16, acc[i][j], 68, wmma::mem_row_major);
        __syncthreads();
#pragma unroll
        for (int it = 0; it < 8; it++) {
            int idx = it * 128 + tid;
            int r = idx >> 5;
            int c4 = (idx & 31) * 4;
            int wmg = r >> 4, rr = r & 15;
            int wng = c4 >> 6, cc = c4 & 63;
            const float* sp = stg + (wng * 2 + wmg) * 1088 + rr * 68 + cc;
            int row = crow + wmg * 32 + i * 16 + rr;
            int colb = ccol + c4;
            float4 bvv = *reinterpret_cast<const float4*>(&bias[colb]);
            float v0 = sp[0] + bvv.x, v1 = sp[1] + bvv.y;
            float v2 = sp[2] + bvv.z, v3 = sp[3] + bvv.w;
            if (ACT == 1) {
                v0 = 0.5f * v0 * (1.0f + erff(v0 * 0.70710678118654752f));
                v1 = 0.5f * v1 * (1.0f + erff(v1 * 0.70710678118654752f));
                v2 = 0.5f * v2 * (1.0f + erff(v2 * 0.70710678118654752f));
                v3 = 0.5f * v3 * (1.0f + erff(v3 * 0.70710678118654752f));
            }
            __half2 h0 = __floats2half2_rn(v0, v1);
            __half2 h1 = __floats2half2_rn(v2, v3);
            *reinterpret_cast<uint2*>(&C[(size_t)row * ldc + colb]) =
                make_uint2(*(uint32_t*)&h0, *(uint32_t*)&h1);
        }
    }
}

// ================= fused attention: q-tile 32, 2 CTA/SM =================
#define ATT_SLD 516
#define ATT_PLD 528
#define ATT_BYTES (32*ATT_SLD*4 + 32*ATT_PLD*2)

__global__ __launch_bounds__(256, 2)
void attn_fused(const __half* __restrict__ QKV, __half* __restrict__ O) {
    extern __shared__ char sm[];
    float* Ssm = reinterpret_cast<float*>(sm);
    __half* Psm = reinterpret_cast<__half*>(sm + 32 * ATT_SLD * 4);

    const int tid = threadIdx.x;
    const int wid = tid >> 5, lane = tid & 31;
    const int bh = blockIdx.y;
    const int b = bh >> 3, h = bh & 7;
    const int q0 = blockIdx.x * 32;

    const __half* qb = QKV + (size_t)b * Sq * QKVLD + h * DKh;
    const __half* kb = QKV + (size_t)b * Sq * QKVLD + 512 + h * DKh;
    const __half* vb = QKV + (size_t)b * Sq * QKVLD + 1024 + h * DKh;

    {
        const int wq = wid & 1, wk = wid >> 1;
        wmma::fragment<wmma::accumulator, 16, 16, 16, float> acc[8];
#pragma unroll
        for (int j = 0; j < 8; j++) wmma::fill_fragment(acc[j], 0.f);

#pragma unroll
        for (int d0 = 0; d0 < DKh; d0 += 16) {
            wmma::fragment<wmma::matrix_a, 16, 16, 16, __half, wmma::row_major> af;
            wmma::load_matrix_sync(af, &qb[(size_t)(q0 + wq * 16) * QKVLD + d0], QKVLD);
#pragma unroll
            for (int j = 0; j < 8; j++) {
                wmma::fragment<wmma::matrix_b, 16, 16, 16, __half, wmma::col_major> bf;
                wmma::load_matrix_sync(bf, &kb[(size_t)(wk * 128 + j * 16) * QKVLD + d0], QKVLD);
                wmma::mma_sync(acc[j], af, bf, acc[j]);
            }
        }
#pragma unroll
        for (int j = 0; j < 8; j++) {
#pragma unroll
            for (int e = 0; e < acc[j].num_elements; e++) acc[j].x[e] *= 0.125f;
            wmma::store_matrix_sync(&Ssm[(wq * 16) * ATT_SLD + wk * 128 + j * 16],
                                    acc[j], ATT_SLD, wmma::mem_row_major);
        }
    }
    __syncthreads();

    {
        const int row = wid * 4 + (lane >> 3);
        const int sub = lane & 7;
        const float* srow = Ssm + row * ATT_SLD;
        __half* prow = Psm + row * ATT_PLD;

        float mx = -1e30f;
#pragma unroll 8
        for (int i = 0; i < 64; i++) mx = fmaxf(mx, srow[sub + 8 * i]);
        mx = fmaxf(mx, __shfl_xor_sync(0xffffffffu, mx, 1));
        mx = fmaxf(mx, __shfl_xor_sync(0xffffffffu, mx, 2));
        mx = fmaxf(mx, __shfl_xor_sync(0xffffffffu, mx, 4));

        float sum = 0.f;
#pragma unroll 8
        for (int i = 0; i < 64; i++) {
            float e = __expf(srow[sub + 8 * i] - mx);
            sum += e;
            prow[sub + 8 * i] = __float2half(e);
        }
        sum += __shfl_xor_sync(0xffffffffu, sum, 1);
        sum += __shfl_xor_sync(0xffffffffu, sum, 2);
        sum += __shfl_xor_sync(0xffffffffu, sum, 4);
        float inv = 1.0f / sum;
#pragma unroll 8
        for (int i = 0; i < 64; i++) {
            int c = sub + 8 * i;
            prow[c] = __float2half(__half2float(prow[c]) * inv);
        }
    }
    __syncthreads();

    {
        const int wq = wid & 1, wd = wid >> 1;
        wmma::fragment<wmma::accumulator, 16, 16, 16, float> acc;
        wmma::fill_fragment(acc, 0.f);

        for (int k0 = 0; k0 < Sq; k0 += 16) {
            wmma::fragment<wmma::matrix_a, 16, 16, 16, __half, wmma::row_major> af;
            wmma::fragment<wmma::matrix_b, 16, 16, 16, __half, wmma::row_major> bf;
            wmma::load_matrix_sync(af, &Psm[(wq * 16) * ATT_PLD + k0], ATT_PLD);
            wmma::load_matrix_sync(bf, &vb[(size_t)k0 * QKVLD + wd * 16], QKVLD);
            wmma::mma_sync(acc, af, bf, acc);
        }
        float* stg = Ssm;
        wmma::store_matrix_sync(&stg[(wq * 16) * 68 + wd * 16], acc, 68, wmma::mem_row_major);
    }
    __syncthreads();
    {
        float* stg = Ssm;
        __half* ob = O + (size_t)b * Sq * Dm + h * DKh;
#pragma unroll
        for (int it = 0; it < 4; it++) {
            int idx = it * 256 + tid;
            int r = idx >> 5, c2 = idx & 31;
            __half2 hh = __floats2half2_rn(stg[r * 68 + c2 * 2], stg[r * 68 + c2 * 2 + 1]);
            *reinterpret_cast<uint32_t*>(&ob[(size_t)(q0 + r) * Dm + c2 * 2]) = *(uint32_t*)&hh;
        }
    }
}

// ================= warp-per-row LayerNorm =================
__global__ __launch_bounds__(256)
void ln_kernel(const __half* __restrict__ a, const __half* __restrict__ res,
               const float* __restrict__ g, const float* __restrict__ beta,
               __half* __restrict__ out) {
    const int wid = threadIdx.x >> 5, lane = threadIdx.x & 31;
    const size_t row = blockIdx.x * 8 + wid;
    const __half2* a2 = reinterpret_cast<const __half2*>(a + row * Dm);
    const __half2* r2 = res ? reinterpret_cast<const __half2*>(res + row * Dm) : nullptr;

    float v[16];
    float s = 0.f, sq = 0.f;
#pragma unroll
    for (int k = 0; k < 8; k++) {
        int i = lane + 32 * k;
        __half2 h = a2[i];
        float x0 = __half2float(__low2half(h)), x1 = __half2float(__high2half(h));
        if (r2) {
            __half2 rr = r2[i];
            x0 += __half2float(__low2half(rr));
            x1 += __half2float(__high2half(rr));
        }
        v[2 * k] = x0; v[2 * k + 1] = x1;
        s += x0 + x1;
        sq += x0 * x0 + x1 * x1;
    }
#pragma unroll
    for (int o = 16; o; o >>= 1) {
        s  += __shfl_xor_sync(0xffffffffu, s, o);
        sq += __shfl_xor_sync(0xffffffffu, sq, o);
    }
    float mean = s * (1.0f / Dm);
    float var = sq * (1.0f / Dm) - mean * mean;
    float inv = rsqrtf(var + 1e-5f);

    const float2* gf = reinterpret_cast<const float2*>(g);
    const float2* bf = reinterpret_cast<const float2*>(beta);
    __half2* o2 = reinterpret_cast<__half2*>(out + row * Dm);
#pragma unroll
    for (int k = 0; k < 8; k++) {
        int i = lane + 32 * k;
        float2 gg = gf[i], bb = bf[i];
        float y0 = (v[2 * k]     - mean) * inv * gg.x + bb.x;
        float y1 = (v[2 * k + 1] - mean) * inv * gg.y + bb.y;
        o2[i] = __floats2half2_rn(y0, y1);
    }
}

// ================= orchestration =================
extern "C" void kernel_launch(void* const* d_in, const int* in_sizes, int n_in,
                              void* d_out, int out_size) {
    const int*   ids  = (const int*)  d_in[0];
    const float* tok  = (const float*)d_in[1];
    const float* pos  = (const float*)d_in[2];
    const float* Wq   = (const float*)d_in[3];
    const float* bq   = (const float*)d_in[4];
    const float* Wk   = (const float*)d_in[5];
    const float* bk   = (const float*)d_in[6];
    const float* Wv   = (const float*)d_in[7];
    const float* bv   = (const float*)d_in[8];
    const float* Wo   = (const float*)d_in[9];
    const float* bo   = (const float*)d_in[10];
    const float* ln_g = (const float*)d_in[11];
    const float* ln_b = (const float*)d_in[12];
    const float* W1   = (const float*)d_in[13];
    const float* b1   = (const float*)d_in[14];
    const float* W2   = (const float*)d_in[15];
    const float* b2   = (const float*)d_in[16];
    const float* on_g = (const float*)d_in[17];
    const float* on_b = (const float*)d_in[18];
    const float* Wout = (const float*)d_in[19];
    const float* bout = (const float*)d_in[20];
    float* out = (float*)d_out;

    __half *x, *qkv, *t, *tmp, *ff, *wqkv, *wo, *w1, *w2, *wout;
    float *bqkv, *boutp;
    cudaGetSymbolAddress((void**)&x,     g_x);
    cudaGetSymbolAddress((void**)&qkv,   g_qkv);
    cudaGetSymbolAddress((void**)&t,     g_t);
    cudaGetSymbolAddress((void**)&tmp,   g_tmp);
    cudaGetSymbolAddress((void**)&ff,    g_ff);
    cudaGetSymbolAddress((void**)&wqkv,  g_wqkv);
    cudaGetSymbolAddress((void**)&wo,    g_wo);
    cudaGetSymbolAddress((void**)&w1,    g_w1);
    cudaGetSymbolAddress((void**)&w2,    g_w2);
    cudaGetSymbolAddress((void**)&wout,  g_wout);
    cudaGetSymbolAddress((void**)&bqkv,  g_bqkv);
    cudaGetSymbolAddress((void**)&boutp, g_bout);

    cudaFuncSetAttribute(gemm_h4<0,0>, cudaFuncAttributeMaxDynamicSharedMemorySize, H4_BYTES);
    cudaFuncSetAttribute(gemm_h4<1,1>, cudaFuncAttributeMaxDynamicSharedMemorySize, H4_BYTES);
    cudaFuncSetAttribute(gemm_h3<0>,   cudaFuncAttributeMaxDynamicSharedMemorySize, H3_BYTES);
    cudaFuncSetAttribute(attn_fused,   cudaFuncAttributeMaxDynamicSharedMemorySize, ATT_BYTES);

    // ---- prep (2 launches) ----
    prep_all<<<(unsigned)((P_TOT + 255) / 256), 256>>>(
        Wq, Wk, Wv, Wo, W1, W2, bq, bk, bv, wqkv, wo, w1, w2, bqkv);
    pad_cvt_wout<<<4096, 256>>>(Wout, wout, bout, boutp);

    embed_kernel<<<NTOK, 128>>>(ids, tok, pos, x);

    for (int l = 0; l < Lyr; l++) {
        const size_t bOff = (size_t)l * Dm;
        // QKV via h3: grid (12, 32) = 384 CTAs at 3/SM
        gemm_h3<0><<<dim3(QKVLD / 128, NTOK / 64), 128, H3_BYTES>>>(
            Dm, x, wqkv + (size_t)l * Dm * QKVLD, QKVLD,
            bqkv + (size_t)l * QKVLD, qkv, QKVLD);

        attn_fused<<<dim3(Sq / 32, Bsz * Hn), 256, ATT_BYTES>>>(qkv, t);

        gemm_h3<0><<<dim3(Dm / 128, NTOK / 64), 128, H3_BYTES>>>(
            Dm, t, wo + (size_t)l * Dm * Dm, Dm, bo + bOff, tmp, Dm);
        ln_kernel<<<NTOK / 8, 256>>>(x, tmp, ln_g + bOff, ln_b + bOff, x);
    }

    // FFN1 via h4 (BK=32): grid (16, 16)
    gemm_h4<1,1><<<dim3(DFFn / 128, NTOK / 128), 128, H4_BYTES>>>(
        Dm, x, w1, DFFn, b1, ff, DFFn, DFFn);
    gemm_h3<0><<<dim3(Dm / 128, NTOK / 64), 128, H3_BYTES>>>(
        DFFn, ff, w2, Dm, b2, t, Dm);
    ln_kernel<<<NTOK / 8, 256>>>(t, nullptr, on_g, on_b, x);

    // logits via h4 (BK=32): grid (394, 16)
    gemm_h4<0,0><<<dim3(VPAD / 128, NTOK / 128), 128, H4_BYTES>>>(
        Dm, x, wout, VPAD, boutp, out, VOCn, VOCn);
}